// round 14
// baseline (speedup 1.0000x reference)
#include <cuda_runtime.h>
#include <cuda_bf16.h>
#include <math.h>
#include <stdint.h>

// Problem constants
#define NB   128
#define TT   32
#define NTOK (128*33)
#define DF   1280
#define WD   256
#define HH   512
#define VV   32000
#define M_NT (NB*TT)      // 4096
#define G4   2048
#define HSC  127.0f
#define WSC  448.0f
#define NBLK 64           // LSTM worker blocks
#define NPART (VV/64)     // 500 vocab n-tiles (64 wide)

// mega role ranges
#define R_H0    0
#define R_LSTM  32
#define R_CONVW (R_LSTM + NBLK)            // 96
#define R_XWX   (R_CONVW + 250)            // 346
#define N_XWX   1024                       // 32 t-chunks x 32 n-tiles(64)
#define R_VOC   (R_XWX + N_XWX)            // 1370
#define R_END   (R_VOC + TT * NPART)       // 17370

// ---- vocab smem (4-stage, k64 chunks): stage = A 128x80B + B 64x80B
#define V_CH_A  (128 * 80)                 // 10240
#define V_CH_B  (64 * 80)                  // 5120
#define V_STAGE (V_CH_A + V_CH_B)          // 15360
#define V_SR_O  (4 * V_STAGE)              // 61440
// ---- LSTM smem layout: Bs 32*1040 | As 3*128*80
#define L_BS_B  (32 * 1040)
#define L_AS_O  L_BS_B
#define M_SMEM  (V_SR_O + 4 * 128 * 4)     // 63488 <= LSTM's 64000? take max
#define M_SMEM_ALL 64000

// ---------------- device scratch (m-indexed arrays are t-major: m'=t*128+n)
__device__ __nv_bfloat16 g_hb[(size_t)M_NT * HH];
__device__ signed char   g_h8[(size_t)M_NT * HH];
__device__ __nv_bfloat16 g_wt[(size_t)VV * HH];
__device__ signed char   g_w8[(size_t)VV * HH];
__device__ __nv_bfloat16 g_WxiT[(size_t)G4 * WD];
__device__ __nv_bfloat16 g_WhiT[(size_t)G4 * HH];
__device__ __nv_bfloat16 g_xg[(size_t)M_NT * WD];
__device__ float g_XWx[(size_t)M_NT * G4];
__device__ __nv_bfloat16 g_h0b[NB * HH];
__device__ float g_c[NB * HH];
__device__ float g_bi[G4];
__device__ float g_part[(size_t)M_NT * NPART];
__device__ float g_nll[M_NT];
__device__ int   g_rows[M_NT];
__device__ int   g_tgt[M_NT];
__device__ int   g_is64;
__device__ int   g_bar_cnt;
__device__ int   g_bar_phase;
__device__ int   g_w8done[250];
__device__ int   g_h0done;
__device__ int   g_xwx_done[TT];

// ---------------- small helpers ----------------
__device__ __forceinline__ float sigmoidf_(float x) { return 1.f / (1.f + __expf(-x)); }
__device__ __forceinline__ uint32_t smem_u32(const void* p) {
    return (uint32_t)__cvta_generic_to_shared(p);
}
__device__ __forceinline__ void cp16a(uint32_t dst, const void* src) {
    asm volatile("cp.async.cg.shared.global [%0], [%1], 16;"
                 :: "r"(dst), "l"(src));
}
__device__ __forceinline__ void cp_commit() { asm volatile("cp.async.commit_group;"); }
template<int N> __device__ __forceinline__ void cp_wait() {
    asm volatile("cp.async.wait_group %0;" :: "n"(N));
}
__device__ __forceinline__ void ldsm4(uint32_t& r0, uint32_t& r1, uint32_t& r2, uint32_t& r3, uint32_t addr) {
    asm volatile("ldmatrix.sync.aligned.m8n8.x4.shared.b16 {%0,%1,%2,%3}, [%4];"
                 : "=r"(r0), "=r"(r1), "=r"(r2), "=r"(r3) : "r"(addr));
}
__device__ __forceinline__ void ldsm2(uint32_t& r0, uint32_t& r1, uint32_t addr) {
    asm volatile("ldmatrix.sync.aligned.m8n8.x2.shared.b16 {%0,%1}, [%2];"
                 : "=r"(r0), "=r"(r1) : "r"(addr));
}
__device__ __forceinline__ void mma16816(float* c, const uint32_t* a, const uint32_t* b) {
    asm volatile("mma.sync.aligned.m16n8k16.row.col.f32.bf16.bf16.f32 "
                 "{%0,%1,%2,%3}, {%4,%5,%6,%7}, {%8,%9}, {%0,%1,%2,%3};"
                 : "+f"(c[0]), "+f"(c[1]), "+f"(c[2]), "+f"(c[3])
                 : "r"(a[0]), "r"(a[1]), "r"(a[2]), "r"(a[3]), "r"(b[0]), "r"(b[1]));
}
__device__ __forceinline__ void mma16832s8(int* c, const uint32_t* a, const uint32_t* b) {
    asm volatile("mma.sync.aligned.m16n8k32.row.col.s32.s8.s8.s32 "
                 "{%0,%1,%2,%3}, {%4,%5,%6,%7}, {%8,%9}, {%0,%1,%2,%3};"
                 : "+r"(c[0]), "+r"(c[1]), "+r"(c[2]), "+r"(c[3])
                 : "r"(a[0]), "r"(a[1]), "r"(a[2]), "r"(a[3]), "r"(b[0]), "r"(b[1]));
}
__device__ __forceinline__ signed char q8h(float x) {
    return (signed char)__float2int_rn(x * HSC);
}
__device__ __forceinline__ signed char q8w(float x) {
    int v = __float2int_rn(x * WSC);
    v = v > 127 ? 127 : (v < -127 ? -127 : v);
    return (signed char)v;
}

// ---------------- caption dtype detection + index build (t-major) ----------
__global__ void detect_kernel(const unsigned int* __restrict__ w) {
    __shared__ int found;
    if (threadIdx.x == 0) found = 0;
    __syncthreads();
    for (int i = threadIdx.x; i < NTOK / 2; i += blockDim.x)
        if (w[2 * i + 1] != 0u) found = 1;
    __syncthreads();
    if (threadIdx.x == 0) g_is64 = (found == 0) ? 1 : 0;
}

__global__ void build_idx_kernel(const void* __restrict__ caps) {
    int m = blockIdx.x * blockDim.x + threadIdx.x;
    if (m < 250) g_w8done[m] = 0;
    if (m < TT) g_xwx_done[m] = 0;
    if (m == M_NT - 1) { g_bar_cnt = 0; g_bar_phase = 0; g_h0done = 0; }
    if (m >= M_NT) return;
    int t = m >> 7, n = m & 127;            // t-major
    int ci, co;
    if (g_is64) {
        const long long* c = (const long long*)caps;
        ci = (int)c[n * 33 + t];  co = (int)c[n * 33 + t + 1];
    } else {
        const int* c = (const int*)caps;
        ci = c[n * 33 + t];       co = c[n * 33 + t + 1];
    }
    g_rows[m] = ci;  g_tgt[m] = co;
}

// ---------------- merged prep: bias | transT(Wx) | transT(Wh) | gather -----
__global__ void prep_kernel(const float* __restrict__ Wx, const float* __restrict__ Wh,
                            const float* __restrict__ bb, const float* __restrict__ We) {
    __shared__ float tile[32][33];
    int role = blockIdx.x;
    int tid = threadIdx.x;

    if (role == 0) {
        for (int np = tid; np < G4; np += 256) {
            int j = np >> 2, g = np & 3;
            g_bi[np] = bb[g * HH + j];
        }
    } else if (role < 1537) {
        const float* in;
        __nv_bfloat16* out;
        int v, K;
        if (role < 513) { v = role - 1;   in = Wx; out = g_WxiT; K = WD; }
        else            { v = role - 513; in = Wh; out = g_WhiT; K = HH; }
        int np0 = (v & 63) * 32, k0 = (v >> 6) * 32;
        int tx = tid & 31, ty = tid >> 5;
#pragma unroll
        for (int r = 0; r < 4; r++)
            tile[ty + r * 8][tx] = in[(size_t)(k0 + ty + r * 8) * G4 + np0 + tx];
        __syncthreads();
#pragma unroll
        for (int r = 0; r < 4; r++) {
            int npl = ty + r * 8;
            int np = np0 + npl;
            int g = np >> 9, j = np & 511;
            int n = (j << 2) + g;
            out[(size_t)n * K + k0 + tx] = __float2bfloat16(tile[tx][npl]);
        }
    } else {
        int idx = (role - 1537) * 256 + tid;
        int m = idx >> 8, k = idx & (WD - 1);
        g_xg[idx] = __float2bfloat16(We[(size_t)g_rows[m] * WD + k]);
    }
}

// ============================================================================
// MEGA: h0 | LSTM | convW | XWx(128x64) | vocab(128x64), 3 blocks/SM target
// ============================================================================
__global__ void __launch_bounds__(256, 3)
mega_kernel(const float* __restrict__ features, const float* __restrict__ W_proj,
            const float* __restrict__ b_proj,
            const float* __restrict__ Wv, const float* __restrict__ bv) {
    extern __shared__ __align__(16) char dynsm[];
    int role = blockIdx.x;
    int tid = threadIdx.x;
    int lane = tid & 31, wid = tid >> 5;

    if (role < R_LSTM) {
        // ---------------- h0 worker: BM=32 BN=64 BK=16 TM=2 TN=4 -----------
        int r = role - R_H0;
        int m0 = (r >> 3) * 32, n0 = (r & 7) * 64;
        float (*As)[33] = (float (*)[33])dynsm;
        float (*Bs)[64] = (float (*)[64])(dynsm + 16 * 33 * 4);
        int tx = tid & 15, ty = tid >> 4;

        float acc[2][4] = {};
        for (int k0 = 0; k0 < DF; k0 += 16) {
#pragma unroll
            for (int l = 0; l < 2; l++) {
                int idx = tid + l * 256;
                int k = idx & 15, m = idx >> 4;
                As[k][m] = features[(size_t)(m0 + m) * DF + k0 + k];
            }
#pragma unroll
            for (int l = 0; l < 4; l++) {
                int idx = tid + l * 256;
                int n = idx & 63, k = idx >> 6;
                Bs[k][n] = W_proj[(size_t)(k0 + k) * HH + n0 + n];
            }
            __syncthreads();
#pragma unroll
            for (int kk = 0; kk < 16; kk++) {
                float a0 = As[kk][ty * 2], a1 = As[kk][ty * 2 + 1];
                float b[4];
#pragma unroll
                for (int j2 = 0; j2 < 4; j2++) b[j2] = Bs[kk][tx * 4 + j2];
#pragma unroll
                for (int j2 = 0; j2 < 4; j2++) { acc[0][j2] += a0 * b[j2]; acc[1][j2] += a1 * b[j2]; }
            }
            __syncthreads();
        }
#pragma unroll
        for (int i = 0; i < 2; i++)
#pragma unroll
            for (int j2 = 0; j2 < 4; j2++) {
                int n = n0 + tx * 4 + j2;
                g_h0b[(size_t)(m0 + ty * 2 + i) * HH + n] =
                    __float2bfloat16(acc[i][j2] + b_proj[n]);
            }
        __threadfence();
        __syncthreads();
        if (tid == 0) atomicAdd(&g_h0done, 1);

    } else if (role < R_CONVW) {
        // ---------------- LSTM worker ----------------
        uint32_t bsU = smem_u32(dynsm);
        uint32_t asU = bsU + L_AS_O;
        int wm = wid >> 2, wn = wid & 3;
        int n0 = (role - R_LSTM) * 32;

#pragma unroll
        for (int l = 0; l < 8; l++) {
            int idx = tid + l * 256;
            int row = idx >> 6, ch = idx & 63;
            cp16a(bsU + row * 1040 + ch * 16, g_WhiT + (size_t)(n0 + row) * HH + ch * 8);
        }
        cp_commit(); cp_wait<0>();
        __syncthreads();

        if (tid == 0) {
            while (*(volatile int*)&g_h0done < 32) __nanosleep(64);
            __threadfence();
        }
        __syncthreads();

        int cbase = n0 + wn * 8 + 2 * (lane & 3);
        int j = cbase >> 2;

        for (int t = 0; t < TT; t++) {
            const __nv_bfloat16* Aptr = (t == 0) ? g_h0b : (g_hb + (size_t)(t - 1) * 128 * HH);

            auto loadA = [&](int s, int k0) {
#pragma unroll
                for (int l = 0; l < 2; l++) {
                    int idx = tid + l * 256;
                    int row = idx >> 2, ch = idx & 3;
                    cp16a(asU + s * 10240 + row * 80 + ch * 16,
                          Aptr + (size_t)row * HH + k0 + ch * 8);
                }
                cp_commit();
            };

            float acc[4][4];
#pragma unroll
            for (int a = 0; a < 4; a++)
#pragma unroll
                for (int c = 0; c < 4; c++) acc[a][c] = 0.f;

            loadA(0, 0);
            loadA(1, 32);

            for (int it = 0; it < 16; it++) {
                if (it < 15) cp_wait<1>(); else cp_wait<0>();
                __syncthreads();
                if (it + 2 < 16) loadA((it + 2) % 3, (it + 2) * 32);
                int s = it % 3;
#pragma unroll
                for (int ks = 0; ks < 2; ks++) {
                    uint32_t a[4][4], b[2];
#pragma unroll
                    for (int mf = 0; mf < 4; mf++) {
                        int row = wm * 64 + mf * 16 + (lane & 15);
                        ldsm4(a[mf][0], a[mf][1], a[mf][2], a[mf][3],
                              asU + s * 10240 + row * 80 + (ks * 16 + (lane >> 4) * 8) * 2);
                    }
                    {
                        int row = wn * 8 + (lane & 7);
                        ldsm2(b[0], b[1],
                              bsU + row * 1040 + (it * 32 + ks * 16 + ((lane >> 3) & 1) * 8) * 2);
                    }
#pragma unroll
                    for (int mf = 0; mf < 4; mf++)
                        mma16816(acc[mf], a[mf], b);
                }
            }

            if (tid == 0) {
                while (*(volatile int*)&g_xwx_done[t] < 32) __nanosleep(64);
                __threadfence();
            }
            __syncthreads();

#pragma unroll
            for (int mf = 0; mf < 4; mf++) {
                int r = wm * 64 + mf * 16 + (lane >> 2);
                float2 x0 = *(const float2*)&g_XWx[(size_t)(t * 128 + r) * G4 + cbase];
                float2 x1 = *(const float2*)&g_XWx[(size_t)(t * 128 + r + 8) * G4 + cbase];
                float v0 = acc[mf][0] + x0.x, v1 = acc[mf][1] + x0.y;
                float v2 = acc[mf][2] + x1.x, v3 = acc[mf][3] + x1.y;
                float e0 = __shfl_xor_sync(0xffffffffu, v0, 1);
                float e1 = __shfl_xor_sync(0xffffffffu, v1, 1);
                float e2 = __shfl_xor_sync(0xffffffffu, v2, 1);
                float e3 = __shfl_xor_sync(0xffffffffu, v3, 1);
                if (!(lane & 1)) {
                    {
                        float i_ = sigmoidf_(v0), f_ = sigmoidf_(v1);
                        float o_ = sigmoidf_(e0), gg = tanhf(e1);
                        float cp = t ? g_c[r * HH + j] : 0.f;
                        float cn = f_ * cp + i_ * gg;
                        float hv = o_ * tanhf(cn);
                        g_c[r * HH + j] = cn;
                        size_t hi = (size_t)(t * 128 + r) * HH + j;
                        g_hb[hi] = __float2bfloat16(hv);
                        g_h8[hi] = q8h(hv);
                    }
                    {
                        int r8 = r + 8;
                        float i_ = sigmoidf_(v2), f_ = sigmoidf_(v3);
                        float o_ = sigmoidf_(e2), gg = tanhf(e3);
                        float cp = t ? g_c[r8 * HH + j] : 0.f;
                        float cn = f_ * cp + i_ * gg;
                        float hv = o_ * tanhf(cn);
                        g_c[r8 * HH + j] = cn;
                        size_t hi = (size_t)(t * 128 + r8) * HH + j;
                        g_hb[hi] = __float2bfloat16(hv);
                        g_h8[hi] = q8h(hv);
                    }
                }
            }

            __syncthreads();
            if (tid == 0) {
                __threadfence();
                int old = atomicAdd(&g_bar_cnt, 1);
                if (old == NBLK * (t + 1) - 1)
                    atomicExch(&g_bar_phase, t + 1);
                while (*(volatile int*)&g_bar_phase < t + 1) __nanosleep(64);
                __threadfence();
            }
            __syncthreads();
        }
    } else if (role < R_XWX) {
        // ---------------- convW worker ----------------
        int b = role - R_CONVW;
        float (*tile)[33] = (float (*)[33])dynsm;
        int tx = tid & 31, ty = tid >> 5;
        for (int kt = 0; kt < 16; kt++) {
            int k0 = kt * 32;
#pragma unroll
            for (int ns = 0; ns < 4; ns++) {
                int n0b = b * 128 + ns * 32;
                __syncthreads();
#pragma unroll
                for (int r = 0; r < 4; r++)
                    tile[ty + r * 8][tx] = Wv[(size_t)(k0 + ty + r * 8) * VV + n0b + tx];
                __syncthreads();
#pragma unroll
                for (int r = 0; r < 4; r++) {
                    int n = ty + r * 8;
                    float w = tile[tx][n];
                    g_wt[(size_t)(n0b + n) * HH + k0 + tx] = __float2bfloat16(w);
                    g_w8[(size_t)(n0b + n) * HH + k0 + tx] = q8w(w);
                }
            }
        }
        __threadfence();
        __syncthreads();
        if (tid == 0) atomicExch(&g_w8done[b], 1);
    } else if (role < R_VOC) {
        // ---------------- XWx worker: block 128m x 64n, warp tile 64x16 ----
        int v = role - R_XWX;
        int m0 = (v >> 5) * 128, n0 = (v & 31) * 64;   // t-ascending

        uint32_t aU = smem_u32(dynsm);
        uint32_t bU = aU + 2 * 128 * 80;
        int wm = wid & 1, wn = wid >> 1;               // 2m x 4n warps

        float acc[4][2][4];
#pragma unroll
        for (int a = 0; a < 4; a++)
#pragma unroll
            for (int b2 = 0; b2 < 2; b2++)
#pragma unroll
                for (int c = 0; c < 4; c++) acc[a][b2][c] = 0.f;

        auto loadAB = [&](int s, int k0) {
#pragma unroll
            for (int l = 0; l < 2; l++) {              // A: 128 rows x 64B
                int idx = tid + l * 256;
                int row = idx >> 2, ch = idx & 3;
                cp16a(aU + s * 10240 + row * 80 + ch * 16,
                      g_xg + (size_t)(m0 + row) * WD + k0 + ch * 8);
            }
            {                                          // B: 64 rows x 64B
                int row = tid >> 2, ch = tid & 3;
                if (row < 64)
                    cp16a(bU + s * 5120 + row * 80 + ch * 16,
                          g_WxiT + (size_t)(n0 + row) * WD + k0 + ch * 8);
            }
            cp_commit();
        };
        loadAB(0, 0);

        constexpr int NIT = WD / 32;  // 8
        for (int it = 0; it < NIT; it++) {
            if (it + 1 < NIT) {
                loadAB((it + 1) & 1, (it + 1) * 32);
                cp_wait<1>();
            } else cp_wait<0>();
            __syncthreads();
            int s = it & 1;
#pragma unroll
            for (int ks = 0; ks < 2; ks++) {
                uint32_t a[4][4], b[2][2];
#pragma unroll
                for (int mf = 0; mf < 4; mf++) {
                    int row = wm * 64 + mf * 16 + (lane & 15);
                    ldsm4(a[mf][0], a[mf][1], a[mf][2], a[mf][3],
                          aU + s * 10240 + row * 80 + (ks * 16 + (lane >> 4) * 8) * 2);
                }
                {   // paired B: matrices (nf0,kh0),(nf0,kh1),(nf1,kh0),(nf1,kh1)
                    int mI = lane >> 3;
                    int nf_loc = mI >> 1, kh = mI & 1;
                    int row = wn * 16 + nf_loc * 8 + (lane & 7);
                    ldsm4(b[0][0], b[0][1], b[1][0], b[1][1],
                          bU + s * 5120 + row * 80 + (ks * 16 + kh * 8) * 2);
                }
#pragma unroll
                for (int mf = 0; mf < 4; mf++)
#pragma unroll
                    for (int nf = 0; nf < 2; nf++)
                        mma16816(acc[mf][nf], a[mf], b[nf]);
            }
            __syncthreads();
        }

#pragma unroll
        for (int mf = 0; mf < 4; mf++) {
            int r = m0 + wm * 64 + mf * 16 + (lane >> 2);
#pragma unroll
            for (int nf = 0; nf < 2; nf++) {
                int c = n0 + wn * 16 + nf * 8 + 2 * (lane & 3);
                float b0 = g_bi[c], b1 = g_bi[c + 1];
                float2 v0 = {acc[mf][nf][0] + b0, acc[mf][nf][1] + b1};
                float2 v1 = {acc[mf][nf][2] + b0, acc[mf][nf][3] + b1};
                *(float2*)&g_XWx[(size_t)r * G4 + c] = v0;
                *(float2*)&g_XWx[(size_t)(r + 8) * G4 + c] = v1;
            }
        }
        __threadfence();
        __syncthreads();
        if (tid == 0) atomicAdd(&g_xwx_done[v >> 5], 1);
    } else {
        // ---------------- vocab consumer: block 128m x 64n, warp 64x16 -----
        int v = role - R_VOC;
        int t = v / NPART, ntile = v % NPART;
        int m0 = t * 128, n0 = ntile * 64;

        if (tid == 0) {
            while (*(volatile int*)&g_bar_phase < t + 1 ||
                   *(volatile int*)&g_w8done[ntile >> 1] == 0)
                __nanosleep(128);
            __threadfence();
        }
        __syncthreads();

        uint32_t sU = smem_u32(dynsm);
        float (*sred)[128] = (float (*)[128])(dynsm + V_SR_O);
        int wm = wid & 1, wn = wid >> 1;               // 2m x 4n warps

        int acc[4][2][4];
#pragma unroll
        for (int a = 0; a < 4; a++)
#pragma unroll
            for (int b2 = 0; b2 < 2; b2++)
#pragma unroll
                for (int c = 0; c < 4; c++) acc[a][b2][c] = 0;

        auto loadAB = [&](int s, int k0) {
            uint32_t aS = sU + s * V_STAGE;
            uint32_t bS = aS + V_CH_A;
#pragma unroll
            for (int l = 0; l < 2; l++) {              // A: 128 rows x 64B s8
                int idx = tid + l * 256;
                int row = idx >> 2, ch = idx & 3;
                cp16a(aS + row * 80 + ch * 16,
                      g_h8 + (size_t)(m0 + row) * HH + k0 + ch * 16);
            }
            {                                          // B: 64 rows x 64B s8
                int row = tid >> 2, ch = tid & 3;
                if (row < 64)
                    cp16a(bS + row * 80 + ch * 16,
                          g_w8 + (size_t)(n0 + row) * HH + k0 + ch * 16);
            }
            cp_commit();
        };

        loadAB(0, 0);
        loadAB(1, 64);
        loadAB(2, 128);

        constexpr int NCH = HH / 64;  // 8
        for (int c = 0; c < NCH; c++) {
            if (c <= 5) cp_wait<2>();
            else if (c == 6) cp_wait<1>();
            else cp_wait<0>();
            __syncthreads();
            if (c + 3 < NCH) loadAB((c + 3) & 3, (c + 3) * 64);
            uint32_t aS = sU + (c & 3) * V_STAGE;
            uint32_t bS = aS + V_CH_A;
#pragma unroll
            for (int ks = 0; ks < 2; ks++) {
                uint32_t a[4][4], b[2][2];
#pragma unroll
                for (int mf = 0; mf < 4; mf++) {
                    int row = wm * 64 + mf * 16 + (lane & 15);
                    ldsm4(a[mf][0], a[mf][1], a[mf][2], a[mf][3],
                          aS + row * 80 + ks * 32 + (lane >> 4) * 16);
                }
                {   // paired B ldsm4 (s8): (nf0,kh0),(nf0,kh1),(nf1,kh0),(nf1,kh1)
                    int mI = lane >> 3;
                    int nf_loc = mI >> 1, kh = mI & 1;
                    int row = wn * 16 + nf_loc * 8 + (lane & 7);
                    ldsm4(b[0][0], b[0][1], b[1][0], b[1][1],
                          bS + row * 80 + ks * 32 + kh * 16);
                }
#pragma unroll
                for (int mf = 0; mf < 4; mf++)
#pragma unroll
                    for (int nf = 0; nf < 2; nf++)
                        mma16832s8(acc[mf][nf], a[mf], b[nf]);
            }
        }

        const float INV = 1.f / (HSC * WSC);
        float rowsum[4][2] = {};
#pragma unroll
        for (int nf = 0; nf < 2; nf++) {
            int nb_ = n0 + wn * 16 + nf * 8 + 2 * (lane & 3);
            float b0 = bv[nb_], b1 = bv[nb_ + 1];
#pragma unroll
            for (int mf = 0; mf < 4; mf++) {
                rowsum[mf][0] += __expf(fmaf((float)acc[mf][nf][0], INV, b0))
                               + __expf(fmaf((float)acc[mf][nf][1], INV, b1));
                rowsum[mf][1] += __expf(fmaf((float)acc[mf][nf][2], INV, b0))
                               + __expf(fmaf((float)acc[mf][nf][3], INV, b1));
            }
        }
#pragma unroll
        for (int mf = 0; mf < 4; mf++)
#pragma unroll
            for (int h = 0; h < 2; h++) {
                rowsum[mf][h] += __shfl_xor_sync(0xffffffffu, rowsum[mf][h], 1);
                rowsum[mf][h] += __shfl_xor_sync(0xffffffffu, rowsum[mf][h], 2);
            }
        __syncthreads();
        if ((lane & 3) == 0) {
#pragma unroll
            for (int mf = 0; mf < 4; mf++) {
                int r = wm * 64 + mf * 16 + (lane >> 2);
                sred[wn][r]     = rowsum[mf][0];
                sred[wn][r + 8] = rowsum[mf][1];
            }
        }
        __syncthreads();
        if (tid < 128) {
            float s = sred[0][tid] + sred[1][tid] + sred[2][tid] + sred[3][tid];
            g_part[(size_t)(m0 + tid) * NPART + ntile] = s;
        }
    }
}

// ---------------- merged target-score + nll ----------------
__global__ void nll_tsc_kernel(const float* __restrict__ bv) {
    int w = (blockIdx.x * blockDim.x + threadIdx.x) >> 5;
    int lane = threadIdx.x & 31;
    if (w >= M_NT) return;
    int tgt = g_tgt[w];

    const uint4* h4 = (const uint4*)(g_hb + (size_t)w * HH);
    const uint4* w4 = (const uint4*)(g_wt + (size_t)tgt * HH);
    float ts = 0.f;
#pragma unroll
    for (int i = 0; i < 2; i++) {
        uint4 a = h4[lane + i * 32];
        uint4 b = w4[lane + i * 32];
        const uint32_t* ap = &a.x;
        const uint32_t* bp = &b.x;
#pragma unroll
        for (int q = 0; q < 4; q++) {
            float2 fa = __bfloat1622float2(*(const __nv_bfloat162*)&ap[q]);
            float2 fb = __bfloat1622float2(*(const __nv_bfloat162*)&bp[q]);
            ts += fa.x * fb.x + fa.y * fb.y;
        }
    }
    const float* p = g_part + (size_t)w * NPART;
    float se = 0.f;
    for (int i = lane; i < NPART; i += 32) se += p[i];
#pragma unroll
    for (int off = 16; off; off >>= 1) {
        ts += __shfl_down_sync(0xffffffffu, ts, off);
        se += __shfl_down_sync(0xffffffffu, se, off);
    }
    if (lane == 0)
        g_nll[w] = (tgt != 0) ? (logf(se) - (ts + bv[tgt])) : 0.f;
}

__global__ void loss_kernel(float* __restrict__ out) {
    __shared__ float sm[256];
    float s = 0.f;
    for (int i = threadIdx.x; i < M_NT; i += 256) s += g_nll[i];
    sm[threadIdx.x] = s;
    __syncthreads();
    for (int off = 128; off; off >>= 1) {
        if (threadIdx.x < off) sm[threadIdx.x] += sm[threadIdx.x + off];
        __syncthreads();
    }
    if (threadIdx.x == 0) out[0] = sm[0] / (float)NB;
}

// ---------------- launch ----------------
extern "C" void kernel_launch(void* const* d_in, const int* in_sizes, int n_in,
                              void* d_out, int out_size) {
    const float* features = (const float*)d_in[0];
    const void*  captions =               d_in[1];
    const float* W_proj   = (const float*)d_in[2];
    const float* b_proj   = (const float*)d_in[3];
    const float* W_embed  = (const float*)d_in[4];
    const float* Wx       = (const float*)d_in[5];
    const float* Wh       = (const float*)d_in[6];
    const float* bb       = (const float*)d_in[7];
    const float* W_vocab  = (const float*)d_in[8];
    const float* b_vocab  = (const float*)d_in[9];
    float* out = (float*)d_out;

    cudaFuncSetAttribute(mega_kernel,
                         cudaFuncAttributeMaxDynamicSharedMemorySize, M_SMEM_ALL);

    // 0. indices + flag resets, merged prep
    detect_kernel<<<1, 256>>>((const unsigned int*)captions);
    build_idx_kernel<<<(M_NT + 255) / 256, 256>>>(captions);
    prep_kernel<<<1537 + M_NT * WD / 256, 256>>>(Wx, Wh, bb, W_embed);

    // 1. MEGA: h0 + LSTM + convW + XWx + vocab, overlapped via progress flags
    mega_kernel<<<R_END, 256, M_SMEM_ALL>>>(features, W_proj, b_proj, W_vocab, b_vocab);

    // 2. merged tscore+nll, final loss
    nll_tsc_kernel<<<M_NT / 4, 128>>>(b_vocab);
    loss_kernel<<<1, 256>>>(out);
}

// round 15
// speedup vs baseline: 1.2001x; 1.2001x over previous
#include <cuda_runtime.h>
#include <cuda_bf16.h>
#include <math.h>
#include <stdint.h>

// Problem constants
#define NB   128
#define TT   32
#define NTOK (128*33)
#define DF   1280
#define WD   256
#define HH   512
#define VV   32000
#define M_NT (NB*TT)      // 4096
#define G4   2048
#define VBM  128
#define VBN  128
#define NTILES_V (VV/VBN) // 250
#define HSC  127.0f
#define WSC  448.0f
#define NBLK 64           // LSTM worker blocks

// mega role ranges
#define R_H0    0
#define R_LSTM  32
#define R_CONVW (R_LSTM + NBLK)            // 96
#define R_XWX   (R_CONVW + NTILES_V)       // 346
#define R_VOC   (R_XWX + 512)              // 858
#define R_END   (R_VOC + TT * NTILES_V)    // 8858

// ---- vocab smem (4-stage, k64 chunks): A 4x10240 | B 4x10240 | sred
#define V_ST    10240
#define V_AS_B  (4 * V_ST)                 // 40960
#define V_BS_B  (4 * V_ST)                 // 40960
#define V_SR_O  (V_AS_B + V_BS_B)          // 81920
// ---- LSTM smem layout: Bs 32*1040 | As 3*128*80 = 64000 (fits)
#define L_BS_B  (32 * 1040)
#define L_AS_O  L_BS_B
#define M_SMEM  (V_SR_O + 4 * VBM * 4)     // 83968 (max over all roles)

// ---------------- device scratch (m-indexed arrays are t-major: m'=t*128+n)
__device__ __nv_bfloat16 g_hb[(size_t)M_NT * HH];
__device__ signed char   g_h8[(size_t)M_NT * HH];
__device__ __nv_bfloat16 g_wt[(size_t)VV * HH];
__device__ signed char   g_w8[(size_t)VV * HH];
__device__ __nv_bfloat16 g_WxiT[(size_t)G4 * WD];
__device__ __nv_bfloat16 g_WhiT[(size_t)G4 * HH];
__device__ __nv_bfloat16 g_xg[(size_t)M_NT * WD];
__device__ float g_XWx[(size_t)M_NT * G4];
__device__ __nv_bfloat16 g_h0b[NB * HH];
__device__ float g_c[NB * HH];
__device__ float g_bi[G4];
__device__ float g_part[(size_t)M_NT * NTILES_V];
__device__ float g_nll[M_NT];
__device__ int   g_rows[M_NT];
__device__ int   g_tgt[M_NT];
__device__ int   g_is64;
__device__ int   g_bar_cnt;
__device__ int   g_bar_phase;
__device__ int   g_w8done[NTILES_V];
__device__ int   g_h0done;
__device__ int   g_xwx_done[TT];

// ---------------- small helpers ----------------
__device__ __forceinline__ float sigmoidf_(float x) { return 1.f / (1.f + __expf(-x)); }
__device__ __forceinline__ uint32_t smem_u32(const void* p) {
    return (uint32_t)__cvta_generic_to_shared(p);
}
__device__ __forceinline__ void cp16a(uint32_t dst, const void* src) {
    asm volatile("cp.async.cg.shared.global [%0], [%1], 16;"
                 :: "r"(dst), "l"(src));
}
__device__ __forceinline__ void cp_commit() { asm volatile("cp.async.commit_group;"); }
template<int N> __device__ __forceinline__ void cp_wait() {
    asm volatile("cp.async.wait_group %0;" :: "n"(N));
}
__device__ __forceinline__ void ldsm4(uint32_t& r0, uint32_t& r1, uint32_t& r2, uint32_t& r3, uint32_t addr) {
    asm volatile("ldmatrix.sync.aligned.m8n8.x4.shared.b16 {%0,%1,%2,%3}, [%4];"
                 : "=r"(r0), "=r"(r1), "=r"(r2), "=r"(r3) : "r"(addr));
}
__device__ __forceinline__ void ldsm2(uint32_t& r0, uint32_t& r1, uint32_t addr) {
    asm volatile("ldmatrix.sync.aligned.m8n8.x2.shared.b16 {%0,%1}, [%2];"
                 : "=r"(r0), "=r"(r1) : "r"(addr));
}
__device__ __forceinline__ void mma16816(float* c, const uint32_t* a, const uint32_t* b) {
    asm volatile("mma.sync.aligned.m16n8k16.row.col.f32.bf16.bf16.f32 "
                 "{%0,%1,%2,%3}, {%4,%5,%6,%7}, {%8,%9}, {%0,%1,%2,%3};"
                 : "+f"(c[0]), "+f"(c[1]), "+f"(c[2]), "+f"(c[3])
                 : "r"(a[0]), "r"(a[1]), "r"(a[2]), "r"(a[3]), "r"(b[0]), "r"(b[1]));
}
__device__ __forceinline__ void mma16832s8(int* c, const uint32_t* a, const uint32_t* b) {
    asm volatile("mma.sync.aligned.m16n8k32.row.col.s32.s8.s8.s32 "
                 "{%0,%1,%2,%3}, {%4,%5,%6,%7}, {%8,%9}, {%0,%1,%2,%3};"
                 : "+r"(c[0]), "+r"(c[1]), "+r"(c[2]), "+r"(c[3])
                 : "r"(a[0]), "r"(a[1]), "r"(a[2]), "r"(a[3]), "r"(b[0]), "r"(b[1]));
}
__device__ __forceinline__ signed char q8h(float x) {
    return (signed char)__float2int_rn(x * HSC);
}
__device__ __forceinline__ signed char q8w(float x) {
    int v = __float2int_rn(x * WSC);
    v = v > 127 ? 127 : (v < -127 ? -127 : v);
    return (signed char)v;
}

// ---------------- caption dtype detection + index build (t-major) ----------
__global__ void detect_kernel(const unsigned int* __restrict__ w) {
    __shared__ int found;
    if (threadIdx.x == 0) found = 0;
    __syncthreads();
    for (int i = threadIdx.x; i < NTOK / 2; i += blockDim.x)
        if (w[2 * i + 1] != 0u) found = 1;
    __syncthreads();
    if (threadIdx.x == 0) g_is64 = (found == 0) ? 1 : 0;
}

__global__ void build_idx_kernel(const void* __restrict__ caps) {
    int m = blockIdx.x * blockDim.x + threadIdx.x;
    if (m < NTILES_V) g_w8done[m] = 0;
    if (m < TT) g_xwx_done[m] = 0;
    if (m == M_NT - 1) { g_bar_cnt = 0; g_bar_phase = 0; g_h0done = 0; }
    if (m >= M_NT) return;
    int t = m >> 7, n = m & 127;            // t-major
    int ci, co;
    if (g_is64) {
        const long long* c = (const long long*)caps;
        ci = (int)c[n * 33 + t];  co = (int)c[n * 33 + t + 1];
    } else {
        const int* c = (const int*)caps;
        ci = c[n * 33 + t];       co = c[n * 33 + t + 1];
    }
    g_rows[m] = ci;  g_tgt[m] = co;
}

// ---------------- merged prep: bias | transT(Wx) | transT(Wh) | gather -----
__global__ void prep_kernel(const float* __restrict__ Wx, const float* __restrict__ Wh,
                            const float* __restrict__ bb, const float* __restrict__ We) {
    __shared__ float tile[32][33];
    int role = blockIdx.x;
    int tid = threadIdx.x;

    if (role == 0) {
        for (int np = tid; np < G4; np += 256) {
            int j = np >> 2, g = np & 3;
            g_bi[np] = bb[g * HH + j];
        }
    } else if (role < 1537) {
        const float* in;
        __nv_bfloat16* out;
        int v, K;
        if (role < 513) { v = role - 1;   in = Wx; out = g_WxiT; K = WD; }
        else            { v = role - 513; in = Wh; out = g_WhiT; K = HH; }
        int np0 = (v & 63) * 32, k0 = (v >> 6) * 32;
        int tx = tid & 31, ty = tid >> 5;
#pragma unroll
        for (int r = 0; r < 4; r++)
            tile[ty + r * 8][tx] = in[(size_t)(k0 + ty + r * 8) * G4 + np0 + tx];
        __syncthreads();
#pragma unroll
        for (int r = 0; r < 4; r++) {
            int npl = ty + r * 8;
            int np = np0 + npl;
            int g = np >> 9, j = np & 511;
            int n = (j << 2) + g;
            out[(size_t)n * K + k0 + tx] = __float2bfloat16(tile[tx][npl]);
        }
    } else {
        int idx = (role - 1537) * 256 + tid;
        int m = idx >> 8, k = idx & (WD - 1);
        g_xg[idx] = __float2bfloat16(We[(size_t)g_rows[m] * WD + k]);
    }
}

// ============================================================================
// MEGA: h0 [0,32) | LSTM [32,96) | convW [96,346) | XWx [346,858) | vocab rest
// ============================================================================
__global__ void __launch_bounds__(256)
mega_kernel(const float* __restrict__ features, const float* __restrict__ W_proj,
            const float* __restrict__ b_proj,
            const float* __restrict__ Wv, const float* __restrict__ bv) {
    extern __shared__ __align__(16) char dynsm[];
    int role = blockIdx.x;
    int tid = threadIdx.x;
    int lane = tid & 31, wid = tid >> 5;

    if (role < R_LSTM) {
        // ---------------- h0 worker: BM=32 BN=64 BK=16 TM=2 TN=4 -----------
        int r = role - R_H0;
        int m0 = (r >> 3) * 32, n0 = (r & 7) * 64;
        float (*As)[33] = (float (*)[33])dynsm;
        float (*Bs)[64] = (float (*)[64])(dynsm + 16 * 33 * 4);
        int tx = tid & 15, ty = tid >> 4;

        float acc[2][4] = {};
        for (int k0 = 0; k0 < DF; k0 += 16) {
#pragma unroll
            for (int l = 0; l < 2; l++) {
                int idx = tid + l * 256;
                int k = idx & 15, m = idx >> 4;
                As[k][m] = features[(size_t)(m0 + m) * DF + k0 + k];
            }
#pragma unroll
            for (int l = 0; l < 4; l++) {
                int idx = tid + l * 256;
                int n = idx & 63, k = idx >> 6;
                Bs[k][n] = W_proj[(size_t)(k0 + k) * HH + n0 + n];
            }
            __syncthreads();
#pragma unroll
            for (int kk = 0; kk < 16; kk++) {
                float a0 = As[kk][ty * 2], a1 = As[kk][ty * 2 + 1];
                float b[4];
#pragma unroll
                for (int j2 = 0; j2 < 4; j2++) b[j2] = Bs[kk][tx * 4 + j2];
#pragma unroll
                for (int j2 = 0; j2 < 4; j2++) { acc[0][j2] += a0 * b[j2]; acc[1][j2] += a1 * b[j2]; }
            }
            __syncthreads();
        }
#pragma unroll
        for (int i = 0; i < 2; i++)
#pragma unroll
            for (int j2 = 0; j2 < 4; j2++) {
                int n = n0 + tx * 4 + j2;
                g_h0b[(size_t)(m0 + ty * 2 + i) * HH + n] =
                    __float2bfloat16(acc[i][j2] + b_proj[n]);
            }
        __threadfence();
        __syncthreads();
        if (tid == 0) atomicAdd(&g_h0done, 1);

    } else if (role < R_CONVW) {
        // ---------------- LSTM worker ----------------
        uint32_t bsU = smem_u32(dynsm);
        uint32_t asU = bsU + L_AS_O;
        int wm = wid >> 2, wn = wid & 3;
        int n0 = (role - R_LSTM) * 32;

#pragma unroll
        for (int l = 0; l < 8; l++) {
            int idx = tid + l * 256;
            int row = idx >> 6, ch = idx & 63;
            cp16a(bsU + row * 1040 + ch * 16, g_WhiT + (size_t)(n0 + row) * HH + ch * 8);
        }
        cp_commit(); cp_wait<0>();
        __syncthreads();

        if (tid == 0) {
            while (*(volatile int*)&g_h0done < 32) __nanosleep(64);
            __threadfence();
        }
        __syncthreads();

        int cbase = n0 + wn * 8 + 2 * (lane & 3);
        int j = cbase >> 2;

        for (int t = 0; t < TT; t++) {
            const __nv_bfloat16* Aptr = (t == 0) ? g_h0b : (g_hb + (size_t)(t - 1) * 128 * HH);

            auto loadA = [&](int s, int k0) {
#pragma unroll
                for (int l = 0; l < 2; l++) {
                    int idx = tid + l * 256;
                    int row = idx >> 2, ch = idx & 3;
                    cp16a(asU + s * 10240 + row * 80 + ch * 16,
                          Aptr + (size_t)row * HH + k0 + ch * 8);
                }
                cp_commit();
            };

            float acc[4][4];
#pragma unroll
            for (int a = 0; a < 4; a++)
#pragma unroll
                for (int c = 0; c < 4; c++) acc[a][c] = 0.f;

            loadA(0, 0);
            loadA(1, 32);

            for (int it = 0; it < 16; it++) {
                if (it < 15) cp_wait<1>(); else cp_wait<0>();
                __syncthreads();
                if (it + 2 < 16) loadA((it + 2) % 3, (it + 2) * 32);
                int s = it % 3;
#pragma unroll
                for (int ks = 0; ks < 2; ks++) {
                    uint32_t a[4][4], b[2];
#pragma unroll
                    for (int mf = 0; mf < 4; mf++) {
                        int row = wm * 64 + mf * 16 + (lane & 15);
                        ldsm4(a[mf][0], a[mf][1], a[mf][2], a[mf][3],
                              asU + s * 10240 + row * 80 + (ks * 16 + (lane >> 4) * 8) * 2);
                    }
                    {
                        int row = wn * 8 + (lane & 7);
                        ldsm2(b[0], b[1],
                              bsU + row * 1040 + (it * 32 + ks * 16 + ((lane >> 3) & 1) * 8) * 2);
                    }
#pragma unroll
                    for (int mf = 0; mf < 4; mf++)
                        mma16816(acc[mf], a[mf], b);
                }
            }

            if (tid == 0) {
                while (*(volatile int*)&g_xwx_done[t] < 16) __nanosleep(64);
                __threadfence();
            }
            __syncthreads();

#pragma unroll
            for (int mf = 0; mf < 4; mf++) {
                int r = wm * 64 + mf * 16 + (lane >> 2);
                float2 x0 = *(const float2*)&g_XWx[(size_t)(t * 128 + r) * G4 + cbase];
                float2 x1 = *(const float2*)&g_XWx[(size_t)(t * 128 + r + 8) * G4 + cbase];
                float v0 = acc[mf][0] + x0.x, v1 = acc[mf][1] + x0.y;
                float v2 = acc[mf][2] + x1.x, v3 = acc[mf][3] + x1.y;
                float e0 = __shfl_xor_sync(0xffffffffu, v0, 1);
                float e1 = __shfl_xor_sync(0xffffffffu, v1, 1);
                float e2 = __shfl_xor_sync(0xffffffffu, v2, 1);
                float e3 = __shfl_xor_sync(0xffffffffu, v3, 1);
                if (!(lane & 1)) {
                    {
                        float i_ = sigmoidf_(v0), f_ = sigmoidf_(v1);
                        float o_ = sigmoidf_(e0), gg = tanhf(e1);
                        float cp = t ? g_c[r * HH + j] : 0.f;
                        float cn = f_ * cp + i_ * gg;
                        float hv = o_ * tanhf(cn);
                        g_c[r * HH + j] = cn;
                        size_t hi = (size_t)(t * 128 + r) * HH + j;
                        g_hb[hi] = __float2bfloat16(hv);
                        g_h8[hi] = q8h(hv);
                    }
                    {
                        int r8 = r + 8;
                        float i_ = sigmoidf_(v2), f_ = sigmoidf_(v3);
                        float o_ = sigmoidf_(e2), gg = tanhf(e3);
                        float cp = t ? g_c[r8 * HH + j] : 0.f;
                        float cn = f_ * cp + i_ * gg;
                        float hv = o_ * tanhf(cn);
                        g_c[r8 * HH + j] = cn;
                        size_t hi = (size_t)(t * 128 + r8) * HH + j;
                        g_hb[hi] = __float2bfloat16(hv);
                        g_h8[hi] = q8h(hv);
                    }
                }
            }

            __syncthreads();
            if (tid == 0) {
                __threadfence();
                int old = atomicAdd(&g_bar_cnt, 1);
                if (old == NBLK * (t + 1) - 1)
                    atomicExch(&g_bar_phase, t + 1);
                while (*(volatile int*)&g_bar_phase < t + 1) __nanosleep(64);
                __threadfence();
            }
            __syncthreads();
        }
    } else if (role < R_XWX) {
        // ---------------- convW worker ----------------
        int b = role - R_CONVW;
        float (*tile)[33] = (float (*)[33])dynsm;
        int tx = tid & 31, ty = tid >> 5;
        for (int kt = 0; kt < 16; kt++) {
            int k0 = kt * 32;
#pragma unroll
            for (int ns = 0; ns < 4; ns++) {
                int n0b = b * 128 + ns * 32;
                __syncthreads();
#pragma unroll
                for (int r = 0; r < 4; r++)
                    tile[ty + r * 8][tx] = Wv[(size_t)(k0 + ty + r * 8) * VV + n0b + tx];
                __syncthreads();
#pragma unroll
                for (int r = 0; r < 4; r++) {
                    int n = ty + r * 8;
                    float w = tile[tx][n];
                    g_wt[(size_t)(n0b + n) * HH + k0 + tx] = __float2bfloat16(w);
                    g_w8[(size_t)(n0b + n) * HH + k0 + tx] = q8w(w);
                }
            }
        }
        __threadfence();
        __syncthreads();
        if (tid == 0) atomicExch(&g_w8done[b], 1);
    } else if (role < R_VOC) {
        // ---------------- XWx worker (t-ascending) ----------------
        int v = role - R_XWX;
        int m0 = (v >> 4) * 128, n0 = (v & 15) * 128;

        uint32_t aU = smem_u32(dynsm);
        uint32_t bU = aU + 2 * 128 * 80;
        int wm = wid & 1, wn = wid >> 1;

        float acc[4][4][4];
#pragma unroll
        for (int a = 0; a < 4; a++)
#pragma unroll
            for (int b2 = 0; b2 < 4; b2++)
#pragma unroll
                for (int c = 0; c < 4; c++) acc[a][b2][c] = 0.f;

        auto loadA = [&](int s, int k0) {
#pragma unroll
            for (int l = 0; l < 2; l++) {
                int idx = tid + l * 256;
                int row = idx >> 2, ch = idx & 3;
                cp16a(aU + s * 10240 + row * 80 + ch * 16,
                      g_xg + (size_t)(m0 + row) * WD + k0 + ch * 8);
            }
        };
        auto loadB = [&](int s, int k0) {
#pragma unroll
            for (int l = 0; l < 2; l++) {
                int idx = tid + l * 256;
                int row = idx >> 2, ch = idx & 3;
                cp16a(bU + s * 10240 + row * 80 + ch * 16,
                      g_WxiT + (size_t)(n0 + row) * WD + k0 + ch * 8);
            }
        };
        loadA(0, 0); loadB(0, 0); cp_commit();

        constexpr int NIT = WD / 32;  // 8
        for (int it = 0; it < NIT; it++) {
            if (it + 1 < NIT) {
                int s = (it + 1) & 1;
                loadA(s, (it + 1) * 32); loadB(s, (it + 1) * 32);
                cp_commit(); cp_wait<1>();
            } else cp_wait<0>();
            __syncthreads();
            int s = it & 1;
#pragma unroll
            for (int ks = 0; ks < 2; ks++) {
                uint32_t a[4][4], b[4][2];
#pragma unroll
                for (int mf = 0; mf < 4; mf++) {
                    int row = wm * 64 + mf * 16 + (lane & 15);
                    ldsm4(a[mf][0], a[mf][1], a[mf][2], a[mf][3],
                          aU + s * 10240 + row * 80 + (ks * 16 + (lane >> 4) * 8) * 2);
                }
#pragma unroll
                for (int nf = 0; nf < 4; nf++) {
                    int row = wn * 32 + nf * 8 + (lane & 7);
                    ldsm2(b[nf][0], b[nf][1],
                          bU + s * 10240 + row * 80 + (ks * 16 + ((lane >> 3) & 1) * 8) * 2);
                }
#pragma unroll
                for (int mf = 0; mf < 4; mf++)
#pragma unroll
                    for (int nf = 0; nf < 4; nf++)
                        mma16816(acc[mf][nf], a[mf], b[nf]);
            }
            __syncthreads();
        }

#pragma unroll
        for (int mf = 0; mf < 4; mf++) {
            int r = m0 + wm * 64 + mf * 16 + (lane >> 2);
#pragma unroll
            for (int nf = 0; nf < 4; nf++) {
                int c = n0 + wn * 32 + nf * 8 + 2 * (lane & 3);
                float b0 = g_bi[c], b1 = g_bi[c + 1];
                float2 v0 = {acc[mf][nf][0] + b0, acc[mf][nf][1] + b1};
                float2 v1 = {acc[mf][nf][2] + b0, acc[mf][nf][3] + b1};
                *(float2*)&g_XWx[(size_t)r * G4 + c] = v0;
                *(float2*)&g_XWx[(size_t)(r + 8) * G4 + c] = v1;
            }
        }
        __threadfence();
        __syncthreads();
        if (tid == 0) atomicAdd(&g_xwx_done[v >> 4], 1);
    } else {
        // -------- vocab consumer (t, ntile): k64 chunks, 4-stage pipeline ---
        int v = role - R_VOC;
        int t = v / NTILES_V, ntile = v % NTILES_V;
        int m0 = t * 128, n0 = ntile * VBN;

        if (tid == 0) {
            while (*(volatile int*)&g_bar_phase < t + 1 ||
                   *(volatile int*)&g_w8done[ntile] == 0)
                __nanosleep(128);
            __threadfence();
        }
        __syncthreads();

        uint32_t aU = smem_u32(dynsm);
        uint32_t bU = aU + V_AS_B;
        float (*sred)[VBM] = (float (*)[VBM])(dynsm + V_SR_O);
        int wm = wid & 1, wn = wid >> 1;

        int acc[4][4][4];
#pragma unroll
        for (int a = 0; a < 4; a++)
#pragma unroll
            for (int b2 = 0; b2 < 4; b2++)
#pragma unroll
                for (int c = 0; c < 4; c++) acc[a][b2][c] = 0;

        auto loadAB = [&](int s, int k0) {
#pragma unroll
            for (int l = 0; l < 2; l++) {
                int idx = tid + l * 256;
                int row = idx >> 2, ch = idx & 3;
                cp16a(aU + s * V_ST + row * 80 + ch * 16,
                      g_h8 + (size_t)(m0 + row) * HH + k0 + ch * 16);
                cp16a(bU + s * V_ST + row * 80 + ch * 16,
                      g_w8 + (size_t)(n0 + row) * HH + k0 + ch * 16);
            }
            cp_commit();
        };

        loadAB(0, 0);
        loadAB(1, 64);
        loadAB(2, 128);

        constexpr int NIT = HH / 64;  // 8
        for (int it = 0; it < NIT; it++) {
            if (it <= 5) cp_wait<2>();          // 2 chunks stay in flight
            else if (it == 6) cp_wait<1>();
            else cp_wait<0>();
            __syncthreads();
            if (it + 3 < NIT) loadAB((it + 3) & 3, (it + 3) * 64);
            int s = it & 3;
#pragma unroll
            for (int ks = 0; ks < 2; ks++) {
                uint32_t a[4][4], b[4][2];
#pragma unroll
                for (int mf = 0; mf < 4; mf++) {
                    int row = wm * 64 + mf * 16 + (lane & 15);
                    ldsm4(a[mf][0], a[mf][1], a[mf][2], a[mf][3],
                          aU + s * V_ST + row * 80 + ks * 32 + (lane >> 4) * 16);
                }
#pragma unroll
                for (int nf = 0; nf < 4; nf++) {
                    int row = wn * 32 + nf * 8 + (lane & 7);
                    ldsm2(b[nf][0], b[nf][1],
                          bU + s * V_ST + row * 80 + ks * 32 + ((lane >> 3) & 1) * 16);
                }
#pragma unroll
                for (int mf = 0; mf < 4; mf++)
#pragma unroll
                    for (int nf = 0; nf < 4; nf++)
                        mma16832s8(acc[mf][nf], a[mf], b[nf]);
            }
        }

        const float INV = 1.f / (HSC * WSC);
        float rowsum[4][2] = {};
#pragma unroll
        for (int nf = 0; nf < 4; nf++) {
            int nb_ = n0 + wn * 32 + nf * 8 + 2 * (lane & 3);
            float b0 = bv[nb_], b1 = bv[nb_ + 1];
#pragma unroll
            for (int mf = 0; mf < 4; mf++) {
                rowsum[mf][0] += __expf(fmaf((float)acc[mf][nf][0], INV, b0))
                               + __expf(fmaf((float)acc[mf][nf][1], INV, b1));
                rowsum[mf][1] += __expf(fmaf((float)acc[mf][nf][2], INV, b0))
                               + __expf(fmaf((float)acc[mf][nf][3], INV, b1));
            }
        }
#pragma unroll
        for (int mf = 0; mf < 4; mf++)
#pragma unroll
            for (int h = 0; h < 2; h++) {
                rowsum[mf][h] += __shfl_xor_sync(0xffffffffu, rowsum[mf][h], 1);
                rowsum[mf][h] += __shfl_xor_sync(0xffffffffu, rowsum[mf][h], 2);
            }
        __syncthreads();
        if ((lane & 3) == 0) {
#pragma unroll
            for (int mf = 0; mf < 4; mf++) {
                int r = wm * 64 + mf * 16 + (lane >> 2);
                sred[wn][r]     = rowsum[mf][0];
                sred[wn][r + 8] = rowsum[mf][1];
            }
        }
        __syncthreads();
        if (tid < VBM) {
            float s = sred[0][tid] + sred[1][tid] + sred[2][tid] + sred[3][tid];
            g_part[(size_t)(m0 + tid) * NTILES_V + ntile] = s;
        }
    }
}

// ---------------- merged target-score + nll ----------------
__global__ void nll_tsc_kernel(const float* __restrict__ bv) {
    int w = (blockIdx.x * blockDim.x + threadIdx.x) >> 5;
    int lane = threadIdx.x & 31;
    if (w >= M_NT) return;
    int tgt = g_tgt[w];

    const uint4* h4 = (const uint4*)(g_hb + (size_t)w * HH);
    const uint4* w4 = (const uint4*)(g_wt + (size_t)tgt * HH);
    float ts = 0.f;
#pragma unroll
    for (int i = 0; i < 2; i++) {
        uint4 a = h4[lane + i * 32];
        uint4 b = w4[lane + i * 32];
        const uint32_t* ap = &a.x;
        const uint32_t* bp = &b.x;
#pragma unroll
        for (int q = 0; q < 4; q++) {
            float2 fa = __bfloat1622float2(*(const __nv_bfloat162*)&ap[q]);
            float2 fb = __bfloat1622float2(*(const __nv_bfloat162*)&bp[q]);
            ts += fa.x * fb.x + fa.y * fb.y;
        }
    }
    const float* p = g_part + (size_t)w * NTILES_V;
    float se = 0.f;
    for (int i = lane; i < NTILES_V; i += 32) se += p[i];
#pragma unroll
    for (int off = 16; off; off >>= 1) {
        ts += __shfl_down_sync(0xffffffffu, ts, off);
        se += __shfl_down_sync(0xffffffffu, se, off);
    }
    if (lane == 0)
        g_nll[w] = (tgt != 0) ? (logf(se) - (ts + bv[tgt])) : 0.f;
}

__global__ void loss_kernel(float* __restrict__ out) {
    __shared__ float sm[256];
    float s = 0.f;
    for (int i = threadIdx.x; i < M_NT; i += 256) s += g_nll[i];
    sm[threadIdx.x] = s;
    __syncthreads();
    for (int off = 128; off; off >>= 1) {
        if (threadIdx.x < off) sm[threadIdx.x] += sm[threadIdx.x + off];
        __syncthreads();
    }
    if (threadIdx.x == 0) out[0] = sm[0] / (float)NB;
}

// ---------------- launch ----------------
extern "C" void kernel_launch(void* const* d_in, const int* in_sizes, int n_in,
                              void* d_out, int out_size) {
    const float* features = (const float*)d_in[0];
    const void*  captions =               d_in[1];
    const float* W_proj   = (const float*)d_in[2];
    const float* b_proj   = (const float*)d_in[3];
    const float* W_embed  = (const float*)d_in[4];
    const float* Wx       = (const float*)d_in[5];
    const float* Wh       = (const float*)d_in[6];
    const float* bb       = (const float*)d_in[7];
    const float* W_vocab  = (const float*)d_in[8];
    const float* b_vocab  = (const float*)d_in[9];
    float* out = (float*)d_out;

    cudaFuncSetAttribute(mega_kernel,
                         cudaFuncAttributeMaxDynamicSharedMemorySize, M_SMEM);

    // 0. indices + flag resets, merged prep
    detect_kernel<<<1, 256>>>((const unsigned int*)captions);
    build_idx_kernel<<<(M_NT + 255) / 256, 256>>>(captions);
    prep_kernel<<<1537 + M_NT * WD / 256, 256>>>(Wx, Wh, bb, W_embed);

    // 1. MEGA: h0 + LSTM + convW + XWx + vocab, overlapped via progress flags
    mega_kernel<<<R_END, 256, M_SMEM>>>(features, W_proj, b_proj, W_vocab, b_vocab);

    // 2. merged tscore+nll, final loss
    nll_tsc_kernel<<<M_NT / 4, 128>>>(b_vocab);
    loss_kernel<<<1, 256>>>(out);
}

// round 17
// speedup vs baseline: 1.2068x; 1.0056x over previous
#include <cuda_runtime.h>
#include <cuda_bf16.h>
#include <math.h>
#include <stdint.h>

// Problem constants
#define NB   128
#define TT   32
#define NTOK (128*33)
#define DF   1280
#define WD   256
#define HH   512
#define VV   32000
#define M_NT (NB*TT)      // 4096
#define G4   2048
#define VBM  128
#define VBN  128
#define NTILES_V (VV/VBN) // 250
#define HSC  127.0f
#define WSC  448.0f
#define NBLK 64           // LSTM worker blocks

// mega role ranges
#define R_H0    0
#define R_LSTM  32
#define R_CONVW (R_LSTM + NBLK)            // 96
#define R_XWX   (R_CONVW + NTILES_V)       // 346
#define R_VOC   (R_XWX + 512)              // 858
#define R_TAIL  (R_VOC + TT * NTILES_V)    // 8858
#define R_LOSS  (R_TAIL + 512)             // 9370
#define R_END   (R_LOSS + 1)               // 9371

// ---- vocab smem (3-stage, k64 chunks): A 3x10240 | B 3x10240 | sred
#define V_ST    10240
#define V_AS_B  (3 * V_ST)                 // 30720
#define V_SR_O  (2 * V_AS_B)               // 61440
// ---- LSTM smem: Bs 32*1040 | As 3*128*80 = 64000
#define L_BS_B  (32 * 1040)
#define L_AS_O  L_BS_B
#define M_SMEM  64000

// ---------------- device scratch (m-indexed arrays are t-major: m'=t*128+n)
__device__ __nv_bfloat16 g_hb[(size_t)M_NT * HH];
__device__ signed char   g_h8[(size_t)M_NT * HH];
__device__ __nv_bfloat16 g_wt[(size_t)VV * HH];
__device__ signed char   g_w8[(size_t)VV * HH];
__device__ __nv_bfloat16 g_WxiT[(size_t)G4 * WD];
__device__ __nv_bfloat16 g_WhiT[(size_t)G4 * HH];
__device__ __nv_bfloat16 g_xg[(size_t)M_NT * WD];
__device__ float g_XWx[(size_t)M_NT * G4];
__device__ __nv_bfloat16 g_h0b[NB * HH];
__device__ float g_c[NB * HH];
__device__ float g_bi[G4];
__device__ float g_part[(size_t)M_NT * NTILES_V];
__device__ float g_nll[M_NT];
__device__ int   g_rows[M_NT];
__device__ int   g_tgt[M_NT];
__device__ int   g_is64;
__device__ int   g_bar_cnt;
__device__ int   g_bar_phase;
__device__ int   g_w8done[NTILES_V];
__device__ int   g_h0done;
__device__ int   g_xwx_done[TT];
__device__ int   g_voc_done[TT];
__device__ int   g_nll_done;

// ---------------- small helpers ----------------
__device__ __forceinline__ float sigmoidf_(float x) { return 1.f / (1.f + __expf(-x)); }
__device__ __forceinline__ uint32_t smem_u32(const void* p) {
    return (uint32_t)__cvta_generic_to_shared(p);
}
__device__ __forceinline__ void cp16a(uint32_t dst, const void* src) {
    asm volatile("cp.async.cg.shared.global [%0], [%1], 16;"
                 :: "r"(dst), "l"(src));
}
__device__ __forceinline__ void cp_commit() { asm volatile("cp.async.commit_group;"); }
template<int N> __device__ __forceinline__ void cp_wait() {
    asm volatile("cp.async.wait_group %0;" :: "n"(N));
}
__device__ __forceinline__ void ldsm4(uint32_t& r0, uint32_t& r1, uint32_t& r2, uint32_t& r3, uint32_t addr) {
    asm volatile("ldmatrix.sync.aligned.m8n8.x4.shared.b16 {%0,%1,%2,%3}, [%4];"
                 : "=r"(r0), "=r"(r1), "=r"(r2), "=r"(r3) : "r"(addr));
}
__device__ __forceinline__ void ldsm2(uint32_t& r0, uint32_t& r1, uint32_t addr) {
    asm volatile("ldmatrix.sync.aligned.m8n8.x2.shared.b16 {%0,%1}, [%2];"
                 : "=r"(r0), "=r"(r1) : "r"(addr));
}
__device__ __forceinline__ void mma16816(float* c, const uint32_t* a, const uint32_t* b) {
    asm volatile("mma.sync.aligned.m16n8k16.row.col.f32.bf16.bf16.f32 "
                 "{%0,%1,%2,%3}, {%4,%5,%6,%7}, {%8,%9}, {%0,%1,%2,%3};"
                 : "+f"(c[0]), "+f"(c[1]), "+f"(c[2]), "+f"(c[3])
                 : "r"(a[0]), "r"(a[1]), "r"(a[2]), "r"(a[3]), "r"(b[0]), "r"(b[1]));
}
__device__ __forceinline__ void mma16832s8(int* c, const uint32_t* a, const uint32_t* b) {
    asm volatile("mma.sync.aligned.m16n8k32.row.col.s32.s8.s8.s32 "
                 "{%0,%1,%2,%3}, {%4,%5,%6,%7}, {%8,%9}, {%0,%1,%2,%3};"
                 : "+r"(c[0]), "+r"(c[1]), "+r"(c[2]), "+r"(c[3])
                 : "r"(a[0]), "r"(a[1]), "r"(a[2]), "r"(a[3]), "r"(b[0]), "r"(b[1]));
}
__device__ __forceinline__ signed char q8h(float x) {
    return (signed char)__float2int_rn(x * HSC);
}
__device__ __forceinline__ signed char q8w(float x) {
    int v = __float2int_rn(x * WSC);
    v = v > 127 ? 127 : (v < -127 ? -127 : v);
    return (signed char)v;
}

// ---------------- caption dtype detection + index build (t-major) ----------
__global__ void detect_kernel(const unsigned int* __restrict__ w) {
    __shared__ int found;
    if (threadIdx.x == 0) found = 0;
    __syncthreads();
    for (int i = threadIdx.x; i < NTOK / 2; i += blockDim.x)
        if (w[2 * i + 1] != 0u) found = 1;
    __syncthreads();
    if (threadIdx.x == 0) g_is64 = (found == 0) ? 1 : 0;
}

__global__ void build_idx_kernel(const void* __restrict__ caps) {
    int m = blockIdx.x * blockDim.x + threadIdx.x;
    if (m < NTILES_V) g_w8done[m] = 0;
    if (m < TT) { g_xwx_done[m] = 0; g_voc_done[m] = 0; }
    if (m == M_NT - 1) { g_bar_cnt = 0; g_bar_phase = 0; g_h0done = 0; g_nll_done = 0; }
    if (m >= M_NT) return;
    int t = m >> 7, n = m & 127;            // t-major
    int ci, co;
    if (g_is64) {
        const long long* c = (const long long*)caps;
        ci = (int)c[n * 33 + t];  co = (int)c[n * 33 + t + 1];
    } else {
        const int* c = (const int*)caps;
        ci = c[n * 33 + t];       co = c[n * 33 + t + 1];
    }
    g_rows[m] = ci;  g_tgt[m] = co;
}

// ---------------- merged prep: bias | transT(Wx) | transT(Wh) | gather -----
__global__ void prep_kernel(const float* __restrict__ Wx, const float* __restrict__ Wh,
                            const float* __restrict__ bb, const float* __restrict__ We) {
    __shared__ float tile[32][33];
    int role = blockIdx.x;
    int tid = threadIdx.x;

    if (role == 0) {
        for (int np = tid; np < G4; np += 256) {
            int j = np >> 2, g = np & 3;
            g_bi[np] = bb[g * HH + j];
        }
    } else if (role < 1537) {
        const float* in;
        __nv_bfloat16* out;
        int v, K;
        if (role < 513) { v = role - 1;   in = Wx; out = g_WxiT; K = WD; }
        else            { v = role - 513; in = Wh; out = g_WhiT; K = HH; }
        int np0 = (v & 63) * 32, k0 = (v >> 6) * 32;
        int tx = tid & 31, ty = tid >> 5;
#pragma unroll
        for (int r = 0; r < 4; r++)
            tile[ty + r * 8][tx] = in[(size_t)(k0 + ty + r * 8) * G4 + np0 + tx];
        __syncthreads();
#pragma unroll
        for (int r = 0; r < 4; r++) {
            int npl = ty + r * 8;
            int np = np0 + npl;
            int g = np >> 9, j = np & 511;
            int n = (j << 2) + g;
            out[(size_t)n * K + k0 + tx] = __float2bfloat16(tile[tx][npl]);
        }
    } else {
        int idx = (role - 1537) * 256 + tid;
        int m = idx >> 8, k = idx & (WD - 1);
        g_xg[idx] = __float2bfloat16(We[(size_t)g_rows[m] * WD + k]);
    }
}

// ============================================================================
// MEGA: h0 | LSTM | convW | XWx | vocab | nll-tail | loss — fully overlapped
// ============================================================================
__global__ void __launch_bounds__(256)
mega_kernel(const float* __restrict__ features, const float* __restrict__ W_proj,
            const float* __restrict__ b_proj,
            const float* __restrict__ Wv, const float* __restrict__ bv,
            float* __restrict__ out) {
    extern __shared__ __align__(16) char dynsm[];
    int role = blockIdx.x;
    int tid = threadIdx.x;
    int lane = tid & 31, wid = tid >> 5;

    if (role < R_LSTM) {
        // ---------------- h0 worker: BM=32 BN=64 BK=16 TM=2 TN=4 -----------
        int r = role - R_H0;
        int m0 = (r >> 3) * 32, n0 = (r & 7) * 64;
        float (*As)[33] = (float (*)[33])dynsm;
        float (*Bs)[64] = (float (*)[64])(dynsm + 16 * 33 * 4);
        int tx = tid & 15, ty = tid >> 4;

        float acc[2][4] = {};
        for (int k0 = 0; k0 < DF; k0 += 16) {
#pragma unroll
            for (int l = 0; l < 2; l++) {
                int idx = tid + l * 256;
                int k = idx & 15, m = idx >> 4;
                As[k][m] = features[(size_t)(m0 + m) * DF + k0 + k];
            }
#pragma unroll
            for (int l = 0; l < 4; l++) {
                int idx = tid + l * 256;
                int n = idx & 63, k = idx >> 6;
                Bs[k][n] = W_proj[(size_t)(k0 + k) * HH + n0 + n];
            }
            __syncthreads();
#pragma unroll
            for (int kk = 0; kk < 16; kk++) {
                float a0 = As[kk][ty * 2], a1 = As[kk][ty * 2 + 1];
                float b[4];
#pragma unroll
                for (int j2 = 0; j2 < 4; j2++) b[j2] = Bs[kk][tx * 4 + j2];
#pragma unroll
                for (int j2 = 0; j2 < 4; j2++) { acc[0][j2] += a0 * b[j2]; acc[1][j2] += a1 * b[j2]; }
            }
            __syncthreads();
        }
#pragma unroll
        for (int i = 0; i < 2; i++)
#pragma unroll
            for (int j2 = 0; j2 < 4; j2++) {
                int n = n0 + tx * 4 + j2;
                g_h0b[(size_t)(m0 + ty * 2 + i) * HH + n] =
                    __float2bfloat16(acc[i][j2] + b_proj[n]);
            }
        __threadfence();
        __syncthreads();
        if (tid == 0) atomicAdd(&g_h0done, 1);

    } else if (role < R_CONVW) {
        // ---------------- LSTM worker ----------------
        uint32_t bsU = smem_u32(dynsm);
        uint32_t asU = bsU + L_AS_O;
        int wm = wid >> 2, wn = wid & 3;
        int n0 = (role - R_LSTM) * 32;

#pragma unroll
        for (int l = 0; l < 8; l++) {
            int idx = tid + l * 256;
            int row = idx >> 6, ch = idx & 63;
            cp16a(bsU + row * 1040 + ch * 16, g_WhiT + (size_t)(n0 + row) * HH + ch * 8);
        }
        cp_commit(); cp_wait<0>();
        __syncthreads();

        if (tid == 0) {
            while (*(volatile int*)&g_h0done < 32) __nanosleep(64);
            __threadfence();
        }
        __syncthreads();

        int cbase = n0 + wn * 8 + 2 * (lane & 3);
        int j = cbase >> 2;

        for (int t = 0; t < TT; t++) {
            const __nv_bfloat16* Aptr = (t == 0) ? g_h0b : (g_hb + (size_t)(t - 1) * 128 * HH);

            auto loadA = [&](int s, int k0) {
#pragma unroll
                for (int l = 0; l < 2; l++) {
                    int idx = tid + l * 256;
                    int row = idx >> 2, ch = idx & 3;
                    cp16a(asU + s * 10240 + row * 80 + ch * 16,
                          Aptr + (size_t)row * HH + k0 + ch * 8);
                }
                cp_commit();
            };

            float acc[4][4];
#pragma unroll
            for (int a = 0; a < 4; a++)
#pragma unroll
                for (int c = 0; c < 4; c++) acc[a][c] = 0.f;

            loadA(0, 0);
            loadA(1, 32);

            for (int it = 0; it < 16; it++) {
                if (it < 15) cp_wait<1>(); else cp_wait<0>();
                __syncthreads();
                if (it + 2 < 16) loadA((it + 2) % 3, (it + 2) * 32);
                int s = it % 3;
#pragma unroll
                for (int ks = 0; ks < 2; ks++) {
                    uint32_t a[4][4], b[2];
#pragma unroll
                    for (int mf = 0; mf < 4; mf++) {
                        int row = wm * 64 + mf * 16 + (lane & 15);
                        ldsm4(a[mf][0], a[mf][1], a[mf][2], a[mf][3],
                              asU + s * 10240 + row * 80 + (ks * 16 + (lane >> 4) * 8) * 2);
                    }
                    {
                        int row = wn * 8 + (lane & 7);
                        ldsm2(b[0], b[1],
                              bsU + row * 1040 + (it * 32 + ks * 16 + ((lane >> 3) & 1) * 8) * 2);
                    }
#pragma unroll
                    for (int mf = 0; mf < 4; mf++)
                        mma16816(acc[mf], a[mf], b);
                }
            }

            if (tid == 0) {
                while (*(volatile int*)&g_xwx_done[t] < 16) __nanosleep(64);
                __threadfence();
            }
            __syncthreads();

#pragma unroll
            for (int mf = 0; mf < 4; mf++) {
                int r = wm * 64 + mf * 16 + (lane >> 2);
                float2 x0 = *(const float2*)&g_XWx[(size_t)(t * 128 + r) * G4 + cbase];
                float2 x1 = *(const float2*)&g_XWx[(size_t)(t * 128 + r + 8) * G4 + cbase];
                float v0 = acc[mf][0] + x0.x, v1 = acc[mf][1] + x0.y;
                float v2 = acc[mf][2] + x1.x, v3 = acc[mf][3] + x1.y;
                float e0 = __shfl_xor_sync(0xffffffffu, v0, 1);
                float e1 = __shfl_xor_sync(0xffffffffu, v1, 1);
                float e2 = __shfl_xor_sync(0xffffffffu, v2, 1);
                float e3 = __shfl_xor_sync(0xffffffffu, v3, 1);
                if (!(lane & 1)) {
                    {
                        float i_ = sigmoidf_(v0), f_ = sigmoidf_(v1);
                        float o_ = sigmoidf_(e0), gg = tanhf(e1);
                        float cp = t ? g_c[r * HH + j] : 0.f;
                        float cn = f_ * cp + i_ * gg;
                        float hv = o_ * tanhf(cn);
                        g_c[r * HH + j] = cn;
                        size_t hi = (size_t)(t * 128 + r) * HH + j;
                        g_hb[hi] = __float2bfloat16(hv);
                        g_h8[hi] = q8h(hv);
                    }
                    {
                        int r8 = r + 8;
                        float i_ = sigmoidf_(v2), f_ = sigmoidf_(v3);
                        float o_ = sigmoidf_(e2), gg = tanhf(e3);
                        float cp = t ? g_c[r8 * HH + j] : 0.f;
                        float cn = f_ * cp + i_ * gg;
                        float hv = o_ * tanhf(cn);
                        g_c[r8 * HH + j] = cn;
                        size_t hi = (size_t)(t * 128 + r8) * HH + j;
                        g_hb[hi] = __float2bfloat16(hv);
                        g_h8[hi] = q8h(hv);
                    }
                }
            }

            __syncthreads();
            if (tid == 0) {
                __threadfence();
                int old = atomicAdd(&g_bar_cnt, 1);
                if (old == NBLK * (t + 1) - 1)
                    atomicExch(&g_bar_phase, t + 1);
                while (*(volatile int*)&g_bar_phase < t + 1) __nanosleep(64);
                __threadfence();
            }
            __syncthreads();
        }
    } else if (role < R_XWX) {
        // ---------------- convW worker ----------------
        int b = role - R_CONVW;
        float (*tile)[33] = (float (*)[33])dynsm;
        int tx = tid & 31, ty = tid >> 5;
        for (int kt = 0; kt < 16; kt++) {
            int k0 = kt * 32;
#pragma unroll
            for (int ns = 0; ns < 4; ns++) {
                int n0b = b * 128 + ns * 32;
                __syncthreads();
#pragma unroll
                for (int r = 0; r < 4; r++)
                    tile[ty + r * 8][tx] = Wv[(size_t)(k0 + ty + r * 8) * VV + n0b + tx];
                __syncthreads();
#pragma unroll
                for (int r = 0; r < 4; r++) {
                    int n = ty + r * 8;
                    float w = tile[tx][n];
                    g_wt[(size_t)(n0b + n) * HH + k0 + tx] = __float2bfloat16(w);
                    g_w8[(size_t)(n0b + n) * HH + k0 + tx] = q8w(w);
                }
            }
        }
        __threadfence();
        __syncthreads();
        if (tid == 0) atomicExch(&g_w8done[b], 1);
    } else if (role < R_VOC) {
        // ---------------- XWx worker (t-ascending) ----------------
        int v = role - R_XWX;
        int m0 = (v >> 4) * 128, n0 = (v & 15) * 128;

        uint32_t aU = smem_u32(dynsm);
        uint32_t bU = aU + 2 * 128 * 80;
        int wm = wid & 1, wn = wid >> 1;

        float acc[4][4][4];
#pragma unroll
        for (int a = 0; a < 4; a++)
#pragma unroll
            for (int b2 = 0; b2 < 4; b2++)
#pragma unroll
                for (int c = 0; c < 4; c++) acc[a][b2][c] = 0.f;

        auto loadA = [&](int s, int k0) {
#pragma unroll
            for (int l = 0; l < 2; l++) {
                int idx = tid + l * 256;
                int row = idx >> 2, ch = idx & 3;
                cp16a(aU + s * 10240 + row * 80 + ch * 16,
                      g_xg + (size_t)(m0 + row) * WD + k0 + ch * 8);
            }
        };
        auto loadB = [&](int s, int k0) {
#pragma unroll
            for (int l = 0; l < 2; l++) {
                int idx = tid + l * 256;
                int row = idx >> 2, ch = idx & 3;
                cp16a(bU + s * 10240 + row * 80 + ch * 16,
                      g_WxiT + (size_t)(n0 + row) * WD + k0 + ch * 8);
            }
        };
        loadA(0, 0); loadB(0, 0); cp_commit();

        constexpr int NIT = WD / 32;  // 8
        for (int it = 0; it < NIT; it++) {
            if (it + 1 < NIT) {
                int s = (it + 1) & 1;
                loadA(s, (it + 1) * 32); loadB(s, (it + 1) * 32);
                cp_commit(); cp_wait<1>();
            } else cp_wait<0>();
            __syncthreads();
            int s = it & 1;
#pragma unroll
            for (int ks = 0; ks < 2; ks++) {
                uint32_t a[4][4], b[4][2];
#pragma unroll
                for (int mf = 0; mf < 4; mf++) {
                    int row = wm * 64 + mf * 16 + (lane & 15);
                    ldsm4(a[mf][0], a[mf][1], a[mf][2], a[mf][3],
                          aU + s * 10240 + row * 80 + (ks * 16 + (lane >> 4) * 8) * 2);
                }
#pragma unroll
                for (int nf = 0; nf < 4; nf++) {
                    int row = wn * 32 + nf * 8 + (lane & 7);
                    ldsm2(b[nf][0], b[nf][1],
                          bU + s * 10240 + row * 80 + (ks * 16 + ((lane >> 3) & 1) * 8) * 2);
                }
#pragma unroll
                for (int mf = 0; mf < 4; mf++)
#pragma unroll
                    for (int nf = 0; nf < 4; nf++)
                        mma16816(acc[mf][nf], a[mf], b[nf]);
            }
            __syncthreads();
        }

#pragma unroll
        for (int mf = 0; mf < 4; mf++) {
            int r = m0 + wm * 64 + mf * 16 + (lane >> 2);
#pragma unroll
            for (int nf = 0; nf < 4; nf++) {
                int c = n0 + wn * 32 + nf * 8 + 2 * (lane & 3);
                float b0 = g_bi[c], b1 = g_bi[c + 1];
                float2 v0 = {acc[mf][nf][0] + b0, acc[mf][nf][1] + b1};
                float2 v1 = {acc[mf][nf][2] + b0, acc[mf][nf][3] + b1};
                *(float2*)&g_XWx[(size_t)r * G4 + c] = v0;
                *(float2*)&g_XWx[(size_t)(r + 8) * G4 + c] = v1;
            }
        }
        __threadfence();
        __syncthreads();
        if (tid == 0) atomicAdd(&g_xwx_done[v >> 4], 1);
    } else if (role < R_TAIL) {
        // -------- vocab consumer (t, ntile): k64 chunks, 3-stage pipeline ---
        int v = role - R_VOC;
        int t = v / NTILES_V, ntile = v % NTILES_V;
        int m0 = t * 128, n0 = ntile * VBN;

        if (tid == 0) {
            while (*(volatile int*)&g_bar_phase < t + 1 ||
                   *(volatile int*)&g_w8done[ntile] == 0)
                __nanosleep(128);
            __threadfence();
        }
        __syncthreads();

        uint32_t aU = smem_u32(dynsm);
        uint32_t bU = aU + V_AS_B;
        float (*sred)[VBM] = (float (*)[VBM])(dynsm + V_SR_O);
        int wm = wid & 1, wn = wid >> 1;

        int acc[4][4][4];
#pragma unroll
        for (int a = 0; a < 4; a++)
#pragma unroll
            for (int b2 = 0; b2 < 4; b2++)
#pragma unroll
                for (int c = 0; c < 4; c++) acc[a][b2][c] = 0;

        auto loadAB = [&](int s, int k0) {
#pragma unroll
            for (int l = 0; l < 2; l++) {
                int idx = tid + l * 256;
                int row = idx >> 2, ch = idx & 3;
                cp16a(aU + s * V_ST + row * 80 + ch * 16,
                      g_h8 + (size_t)(m0 + row) * HH + k0 + ch * 16);
                cp16a(bU + s * V_ST + row * 80 + ch * 16,
                      g_w8 + (size_t)(n0 + row) * HH + k0 + ch * 16);
            }
            cp_commit();
        };

        loadAB(0, 0);
        loadAB(1, 64);

        constexpr int NIT = HH / 64;  // 8
        for (int it = 0; it < NIT; it++) {
            if (it < NIT - 1) cp_wait<1>(); else cp_wait<0>();
            __syncthreads();
            if (it + 2 < NIT) loadAB((it + 2) % 3, (it + 2) * 64);
            int s = it % 3;
#pragma unroll
            for (int ks = 0; ks < 2; ks++) {
                uint32_t a[4][4], b[4][2];
#pragma unroll
                for (int mf = 0; mf < 4; mf++) {
                    int row = wm * 64 + mf * 16 + (lane & 15);
                    ldsm4(a[mf][0], a[mf][1], a[mf][2], a[mf][3],
                          aU + s * V_ST + row * 80 + ks * 32 + (lane >> 4) * 16);
                }
#pragma unroll
                for (int nf = 0; nf < 4; nf++) {
                    int row = wn * 32 + nf * 8 + (lane & 7);
                    ldsm2(b[nf][0], b[nf][1],
                          bU + s * V_ST + row * 80 + ks * 32 + ((lane >> 3) & 1) * 16);
                }
#pragma unroll
                for (int mf = 0; mf < 4; mf++)
#pragma unroll
                    for (int nf = 0; nf < 4; nf++)
                        mma16832s8(acc[mf][nf], a[mf], b[nf]);
            }
        }

        const float INV = 1.f / (HSC * WSC);
        float rowsum[4][2] = {};
#pragma unroll
        for (int nf = 0; nf < 4; nf++) {
            int nb_ = n0 + wn * 32 + nf * 8 + 2 * (lane & 3);
            float b0 = bv[nb_], b1 = bv[nb_ + 1];
#pragma unroll
            for (int mf = 0; mf < 4; mf++) {
                rowsum[mf][0] += __expf(fmaf((float)acc[mf][nf][0], INV, b0))
                               + __expf(fmaf((float)acc[mf][nf][1], INV, b1));
                rowsum[mf][1] += __expf(fmaf((float)acc[mf][nf][2], INV, b0))
                               + __expf(fmaf((float)acc[mf][nf][3], INV, b1));
            }
        }
#pragma unroll
        for (int mf = 0; mf < 4; mf++)
#pragma unroll
            for (int h = 0; h < 2; h++) {
                rowsum[mf][h] += __shfl_xor_sync(0xffffffffu, rowsum[mf][h], 1);
                rowsum[mf][h] += __shfl_xor_sync(0xffffffffu, rowsum[mf][h], 2);
            }
        __syncthreads();
        if ((lane & 3) == 0) {
#pragma unroll
            for (int mf = 0; mf < 4; mf++) {
                int r = wm * 64 + mf * 16 + (lane >> 2);
                sred[wn][r]     = rowsum[mf][0];
                sred[wn][r + 8] = rowsum[mf][1];
            }
        }
        __syncthreads();
        if (tid < VBM) {
            float s = sred[0][tid] + sred[1][tid] + sred[2][tid] + sred[3][tid];
            g_part[(size_t)(m0 + tid) * NTILES_V + ntile] = s;
        }
        __threadfence();
        __syncthreads();
        if (tid == 0) atomicAdd(&g_voc_done[t], 1);
    } else if (role < R_LOSS) {
        // ---------------- nll tail: one warp per token, 8 tokens per block --
        int w0 = (role - R_TAIL) * 8;
        int t = w0 >> 7;
        if (tid == 0) {
            while (*(volatile int*)&g_voc_done[t] < NTILES_V) __nanosleep(128);
            __threadfence();
        }
        __syncthreads();

        int w = w0 + wid;
        int tgt = g_tgt[w];
        const uint4* h4 = (const uint4*)(g_hb + (size_t)w * HH);
        const uint4* w4 = (const uint4*)(g_wt + (size_t)tgt * HH);
        float ts = 0.f;
#pragma unroll
        for (int i = 0; i < 2; i++) {
            uint4 a = h4[lane + i * 32];
            uint4 b = w4[lane + i * 32];
            const uint32_t* ap = &a.x;
            const uint32_t* bp = &b.x;
#pragma unroll
            for (int q = 0; q < 4; q++) {
                float2 fa = __bfloat1622float2(*(const __nv_bfloat162*)&ap[q]);
                float2 fb = __bfloat1622float2(*(const __nv_bfloat162*)&bp[q]);
                ts += fa.x * fb.x + fa.y * fb.y;
            }
        }
        const float* p = g_part + (size_t)w * NTILES_V;
        float se = 0.f;
        for (int i = lane; i < NTILES_V; i += 32) se += p[i];
#pragma unroll
        for (int off = 16; off; off >>= 1) {
            ts += __shfl_down_sync(0xffffffffu, ts, off);
            se += __shfl_down_sync(0xffffffffu, se, off);
        }
        if (lane == 0)
            g_nll[w] = (tgt != 0) ? (logf(se) - (ts + bv[tgt])) : 0.f;
        __threadfence();
        __syncthreads();
        if (tid == 0) atomicAdd(&g_nll_done, 1);
    } else {
        // ---------------- final loss (deterministic fixed-order sum) --------
        if (tid == 0) {
            while (*(volatile int*)&g_nll_done < 512) __nanosleep(128);
            __threadfence();
        }
        __syncthreads();
        __shared__ float sm[256];
        float s = 0.f;
        for (int i = tid; i < M_NT; i += 256) s += g_nll[i];
        sm[tid] = s;
        __syncthreads();
        for (int off = 128; off; off >>= 1) {
            if (tid < off) sm[tid] += sm[tid + off];
            __syncthreads();
        }
        if (tid == 0) out[0] = sm[0] / (float)NB;
    }
}

// ---------------- launch ----------------
extern "C" void kernel_launch(void* const* d_in, const int* in_sizes, int n_in,
                              void* d_out, int out_size) {
    const float* features = (const float*)d_in[0];
    const void*  captions =               d_in[1];
    const float* W_proj   = (const float*)d_in[2];
    const float* b_proj   = (const float*)d_in[3];
    const float* W_embed  = (const float*)d_in[4];
    const float* Wx       = (const float*)d_in[5];
    const float* Wh       = (const float*)d_in[6];
    const float* bb       = (const float*)d_in[7];
    const float* W_vocab  = (const float*)d_in[8];
    const float* b_vocab  = (const float*)d_in[9];
    float* out = (float*)d_out;

    cudaFuncSetAttribute(mega_kernel,
                         cudaFuncAttributeMaxDynamicSharedMemorySize, M_SMEM);

    // 0. indices + flag resets, merged prep
    detect_kernel<<<1, 256>>>((const unsigned int*)captions);
    build_idx_kernel<<<(M_NT + 255) / 256, 256>>>(captions);
    prep_kernel<<<1537 + M_NT * WD / 256, 256>>>(Wx, Wh, bb, W_embed);

    // 1. MEGA: everything else, overlapped via progress flags
    mega_kernel<<<R_END, 256, M_SMEM>>>(features, W_proj, b_proj, W_vocab, b_vocab, out);
}